// round 5
// baseline (speedup 1.0000x reference)
#include <cuda_runtime.h>
#include <stdint.h>

#define LL 401
#define BB 256
#define PLANE (LL * LL)          // 160801
#define BCH 64                   // batches per chunk
#define NCHUNK 4                 // BB / BCH
#define GX ((PLANE + 255) / 256) // 629
#define NBLK (GX * NCHUNK)       // 2516

// ---------------- device-global scratch (no allocations allowed) -------------
__device__ double g_bin[LL];             // per-distance-bin sum of cm
__device__ double g_W;                   // sum cm * same * maskf
__device__ double g_NC;                  // sum relu(cm) * non_conv
__device__ double g_bSame[BB];           // per-batch same*maskf count
__device__ double g_bNc[BB];             // per-batch non_conv count
__device__ unsigned char g_P [BB * LL];  // [b][pos]  bit0=comp bit1=any bit2=f bit3=r
__device__ unsigned char g_PT[LL * BB];  // [pos][b]  transposed copy (ci broadcast)
__device__ unsigned int g_done;          // last-block-done counter (self-resetting)

// ---------------- prep: pack bytes + per-batch counts + zero globals ---------
__global__ void k_prep(const float2* __restrict__ logits, const int* __restrict__ ctcf) {
    int b = blockIdx.x, t = threadIdx.x;
    if (b == 0) {                         // zero accumulators (graph is replayed)
        if (t < LL) g_bin[t] = 0.0;
        if (t == LL) { g_W = 0.0; g_NC = 0.0; }
    }
    __shared__ unsigned char sc[LL];
    __shared__ unsigned long long shw[16];
    unsigned long long pack = 0ull;
    if (t < LL) {
        int idx = b * LL + t;
        float2 l = logits[idx];
        int o = ctcf[idx];
        unsigned c = (l.y > l.x) ? 1u : 0u;      // argmax of 2 logits (tie -> 0)
        unsigned A = (o != 0) ? 1u : 0u;
        unsigned F = (o == 1) ? 1u : 0u;
        unsigned R = (o == -1) ? 1u : 0u;
        unsigned char byte = (unsigned char)(c | (A << 1) | (F << 2) | (R << 3));
        g_P[idx] = byte;
        g_PT[t * BB + b] = byte;
        sc[t] = (unsigned char)c;
        pack = (unsigned long long)c
             | ((unsigned long long)F << 24)
             | ((unsigned long long)R << 36)
             | ((unsigned long long)A << 48);
    }
    __syncthreads();
    if (t < LL - 1) pack |= ((unsigned long long)(sc[t] == sc[t + 1] ? 1u : 0u)) << 12;

#pragma unroll
    for (int o = 16; o > 0; o >>= 1) pack += __shfl_down_sync(0xffffffffu, pack, o);
    if ((t & 31) == 0) shw[t >> 5] = pack;
    __syncthreads();
    if (t == 0) {
        unsigned long long s = 0;
        for (int w = 0; w < 16; w++) s += shw[w];
        double n1  = (double)(s & 0xFFFull);
        double adj = (double)((s >> 12) & 0xFFFull);
        double F   = (double)((s >> 24) & 0xFFFull);
        double R   = (double)((s >> 36) & 0xFFFull);
        double A   = (double)((s >> 48) & 0xFFFull);
        double n0  = (double)LL - n1;
        g_bSame[b] = n0 * n0 + n1 * n1 - (double)LL - 2.0 * adj;  // same & |i-j|>=2
        g_bNc[b]   = A * A - F * R;                               // non_conv count
    }
}

// ---------------- block reduction over 256 threads --------------------------
__device__ __forceinline__ double blockRed256(double v, double* sh) {
    int t = threadIdx.x;
#pragma unroll
    for (int o = 16; o > 0; o >>= 1) v += __shfl_down_sync(0xffffffffu, v, o);
    if ((t & 31) == 0) sh[t >> 5] = v;
    __syncthreads();
    double r;
    if (t < 32) {
        double w = (t < 8) ? sh[t] : 0.0;
#pragma unroll
        for (int o = 4; o > 0; o >>= 1) w += __shfl_down_sync(0xffffffffu, w, o);
        if (t == 0) sh[0] = w;
    }
    __syncthreads();
    r = sh[0];
    __syncthreads();
    return r;
}

// ---------------- main pass + fused finalize --------------------------------
__global__ void __launch_bounds__(256, 4) k_main(const float* __restrict__ cm,
                                                 float* __restrict__ out) {
    int flat = blockIdx.x * 256 + threadIdx.x;
    bool ok = flat < PLANE;
    int fl = ok ? flat : 0;
    int i = fl / LL;
    int j = fl - i * LL;
    int bin = (i > j) ? (i - j) : (j - i);
    unsigned nm = (bin >= 2) ? 0u : 1u;   // OR-mask: kills "same" test when masked

    int b0 = blockIdx.y * BCH;
    const float* p = cm + (size_t)b0 * PLANE + fl;
    const unsigned char* pj  = g_P  + b0 * LL + j;   // coalesced: lane-consecutive bytes
    const unsigned char* ptI = g_PT + i * BB + b0;   // broadcast: same addr all lanes

    float accS = 0.f, accW = 0.f, accNC = 0.f;

    // 16-wide flat load batches: all loads issued before any consume (MLP=16)
    for (int bb = 0; bb < BCH; bb += 16) {
        float v[16];
#pragma unroll
        for (int k = 0; k < 16; k++) v[k] = __ldg(p + (size_t)k * PLANE);
        unsigned cjv[16];
#pragma unroll
        for (int k = 0; k < 16; k++) cjv[k] = pj[k * LL];
        uint4 ciw = *reinterpret_cast<const uint4*>(ptI);

#pragma unroll
        for (int k = 0; k < 16; k++) {
            unsigned word = (k < 4) ? ciw.x : (k < 8) ? ciw.y : (k < 12) ? ciw.z : ciw.w;
            unsigned ci = word >> (8 * (k & 3));
            float vv = v[k];
            accS += vv;
            if ((((ci ^ cjv[k]) | nm) & 1u) == 0u) accW += vv;
            unsigned x = ci & cjv[k];             // bit1 = any_i & any_j
            unsigned y = (ci << 1) & cjv[k];      // bit3 = f_i & r_j (convergent)
            if ((x & ~(y >> 2) & 2u) != 0u) accNC += fmaxf(vv, 0.0f);
        }

        p  += (size_t)16 * PLANE;
        pj += 16 * LL;
        ptI += 16;
    }

    if (ok) atomicAdd(&g_bin[bin], (double)accS);
    if (!ok) { accW = 0.f; accNC = 0.f; }

    // block-reduce the two scalars -> 2 double atomics per block
#pragma unroll
    for (int o = 16; o > 0; o >>= 1) {
        accW  += __shfl_down_sync(0xffffffffu, accW,  o);
        accNC += __shfl_down_sync(0xffffffffu, accNC, o);
    }
    __shared__ double sW[8], sN[8];
    if ((threadIdx.x & 31) == 0) { sW[threadIdx.x >> 5] = accW; sN[threadIdx.x >> 5] = accNC; }
    __syncthreads();
    if (threadIdx.x == 0) {
        double w = 0.0, nn = 0.0;
#pragma unroll
        for (int q = 0; q < 8; q++) { w += sW[q]; nn += sN[q]; }
        atomicAdd(&g_W, w);
        atomicAdd(&g_NC, nn);
    }

    // ---------- last-block-done: fused finalize ----------
    __shared__ bool isLast;
    __threadfence();
    if (threadIdx.x == 0) {
        unsigned v0 = atomicAdd(&g_done, 1u);
        isLast = (v0 == (unsigned)(NBLK - 1));
    }
    __syncthreads();
    if (!isLast) return;
    if (threadIdx.x == 0) g_done = 0;    // reset for next graph replay
    __threadfence();

    {
        __shared__ double sh[8];
        int t = threadIdx.x;
        int t1 = t + 256;

        double bs0 = (t  < LL) ? g_bin[t]  : 0.0;
        double bs1 = (t1 < LL) ? g_bin[t1] : 0.0;
        double cnt0 = (t == 0) ? (double)LL : 2.0 * (double)(LL - t);
        double cnt1 = 2.0 * (double)(LL - t1);
        double mean0 = bs0 / (cnt0 * (double)BB);
        double mean1 = (t1 < LL) ? bs1 / (cnt1 * (double)BB) : 0.0;
        bool va0 = (t  < LL) && (t  >= 2) && isfinite(mean0) && (mean0 > 0.0);
        bool va1 = (t1 < LL)              && isfinite(mean1) && (mean1 > 0.0);
        double w0 = va0 ? 1.0 : 0.0, w1 = va1 ? 1.0 : 0.0;
        double ld0 = log(fmax((double)t, 1.0));
        double ld1 = log((double)t1);
        double lp0 = log((va0 ? mean0 : 1.0) + 1e-6);
        double lp1 = log((va1 ? mean1 : 1.0) + 1e-6);

        double n     = blockRed256(w0 + w1, sh);
        double sx    = blockRed256(w0 * ld0 + w1 * ld1, sh);
        double sy    = blockRed256(w0 * lp0 + w1 * lp1, sh);
        double tm    = blockRed256(((t >= 2 && t < LL) ? bs0 : 0.0) +
                                   ((t1 < LL) ? bs1 : 0.0), sh);
        double sameC = blockRed256(g_bSame[t], sh);     // exactly 256 batches
        double ncC   = blockRed256(g_bNc[t], sh);

        double nsafe = fmax(n, 1.0);
        double xm = sx / nsafe, ym = sy / nsafe;
        double num = blockRed256(w0 * (ld0 - xm) * (lp0 - ym) +
                                 w1 * (ld1 - xm) * (lp1 - ym), sh);
        double den = blockRed256(w0 * (ld0 - xm) * (ld0 - xm) +
                                 w1 * (ld1 - xm) * (ld1 - xm), sh) + 1e-8;

        if (t == 0) {
            double slope = num / den;
            double dist  = (n >= 5.0) ? (slope + 0.85) * (slope + 0.85) : 0.0;

            double ctcf = (ncC < 1.0) ? 0.0 : g_NC / (ncC + 1e-6);

            double diffC   = (double)BB * ((double)LL * LL - 3.0 * LL + 2.0) - sameC;
            double within  = g_W / fmax(sameC, 1.0);
            double between = (tm - g_W) / fmax(diffC, 1.0);
            double ratio   = within / (fabs(between) + 1e-6);
            double comp    = fmax(0.0, 1.5 - ratio);

            out[0] = (float)dist;
            out[1] = (float)ctcf;
            out[2] = (float)comp;
            out[3] = (float)(dist + 0.5 * ctcf + 0.5 * comp);
        }
    }
}

// ---------------- launch ----------------------------------------------------
extern "C" void kernel_launch(void* const* d_in, const int* in_sizes, int n_in,
                              void* d_out, int out_size) {
    const float* cm      = (const float*)d_in[0];
    const float2* logits = (const float2*)d_in[1];
    const int*   ctcf    = (const int*)d_in[2];
    float* out = (float*)d_out;

    k_prep<<<BB, 512>>>(logits, ctcf);
    k_main<<<dim3(GX, NCHUNK), 256>>>(cm, out);
}